// round 1
// baseline (speedup 1.0000x reference)
#include <cuda_runtime.h>
#include <math.h>

// Problem constants
#define BB 4
#define TT 512
#define DD 64
#define KK 192          // 3 expansion terms x 64
#define X_ELEMS (BB*TT*DD)   // 131072

// Scratch (no allocations allowed)
__device__ float g_F[BB * KK * TT];     // k-major feature matrix per batch
__device__ float g_X1[BB * TT * DD];    // intermediate x after iteration 1
__device__ float g_Cov[BB * DD * DD];   // covariance per batch

// ---------------------------------------------------------------------------
// prep: per-row simplex projection + feature construction
//   F[b][k][t]: k in [0,64)  -> sqrt(p_d)
//               k in [64,128)-> c2 / sqrt(p_d)         (c2^2 = eps/2)
//               k in [128,192)-> c3 / sqrt(p_d)^3      (c3^2 = eps^2/8)
// ---------------------------------------------------------------------------
__global__ void prep_kernel(const float* __restrict__ x, float* __restrict__ Fm) {
    const float EPSf = 1e-8f;
    const float C2 = 7.0710678118654755e-05f;   // sqrt(5e-9)
    const float C3 = 3.5355339059327378e-09f;   // sqrt(1.25e-17)
    int row = blockIdx.x;          // b*512 + t
    int d = threadIdx.x;           // 0..63
    float v = x[(row << 6) + d];
    // jax.nn.softplus = max(x,0) + log1p(exp(-|x|))
    float sp = fmaxf(v, 0.0f) + log1pf(expf(-fabsf(v)));

    float s = sp;
    #pragma unroll
    for (int o = 16; o > 0; o >>= 1) s += __shfl_xor_sync(0xffffffffu, s, o);
    __shared__ float sh[2], sh2[2];
    if ((d & 31) == 0) sh[d >> 5] = s;
    __syncthreads();
    float S = sh[0] + sh[1];
    float p = sp / (S + EPSf);
    p = fmaxf(p, EPSf);
    float s2 = p;
    #pragma unroll
    for (int o = 16; o > 0; o >>= 1) s2 += __shfl_xor_sync(0xffffffffu, s2, o);
    if ((d & 31) == 0) sh2[d >> 5] = s2;
    __syncthreads();
    float S2 = sh2[0] + sh2[1];
    p = p / (S2 + EPSf);

    float sq  = sqrtf(p);
    float inv = 1.0f / sq;
    int b = row >> 9, t = row & 511;
    float* Fb = Fm + b * (KK * TT);
    Fb[d * TT + t]          = sq;
    Fb[(64 + d) * TT + t]   = C2 * inv;
    Fb[(128 + d) * TT + t]  = C3 * (inv * inv * inv);
}

__device__ __forceinline__ float logit_of(float inr) {
    inr = fminf(inr, 1.0f - 1e-6f);
    inr = fmaxf(inr, -1.0f + 1e-6f);
    return -2.0f * acosf(inr);   // TEMPERATURE = 1
}

// ---------------------------------------------------------------------------
// attn: fused (inner GEMM -> logits -> softmax -> w@X -> residual mix)
// grid = 4 batches * 32 row-blocks = 128 blocks, 128 threads.
// smem: sF[192][16] | sG[192][128] (reused as sX[128][66]) | sI[16][516] | sRow[16]
// ---------------------------------------------------------------------------
__global__ void __launch_bounds__(128) attn_kernel(
    const float* __restrict__ Fm, const float* __restrict__ xin,
    float* __restrict__ xout, const float* __restrict__ rsp) {
    extern __shared__ float smem[];
    float* sF   = smem;                   // 3072
    float* sG   = smem + KK * 16;         // 24576
    float* sI   = sG + KK * 128;          // 16*516 = 8256
    float* sRow = sI + 16 * 516;          // 16

    int b  = blockIdx.x >> 5;
    int rb = blockIdx.x & 31;
    int r0 = rb * 16;
    const float* Fb = Fm + b * KK * TT;
    const float* xb = xin + b * TT * DD;
    int tid = threadIdx.x;

    // load F rows for this strip; fold term-3 minus sign into the A operand
    for (int i = tid; i < KK * 16; i += 128) {
        int k = i >> 4, r = i & 15;
        float v = Fb[k * TT + r0 + r];
        sF[i] = (k >= 128) ? -v : v;
    }

    int rowg = tid >> 5;   // 0..3  -> rows rowg*4 .. +3
    int colg = tid & 31;   // 0..31 -> cols colg*4 .. +3 (within col tile)
    const float4* sF4 = reinterpret_cast<const float4*>(sF);
    const float4* sG4 = reinterpret_cast<const float4*>(sG);

    for (int jt = 0; jt < TT; jt += 128) {
        __syncthreads();
        // load G column tile (k-major global => coalesced), 192 x 32 float4
        float4* dst = reinterpret_cast<float4*>(sG);
        for (int i = tid; i < KK * 32; i += 128) {
            int k = i >> 5, c4 = i & 31;
            dst[i] = reinterpret_cast<const float4*>(Fb + k * TT + jt)[c4];
        }
        __syncthreads();

        float acc[4][4];
        #pragma unroll
        for (int i = 0; i < 4; i++)
            #pragma unroll
            for (int j = 0; j < 4; j++) acc[i][j] = 0.0f;

        #pragma unroll 4
        for (int k = 0; k < KK; k++) {
            float4 fa = sF4[(k << 2) + rowg];
            float4 gb = sG4[(k << 5) + colg];
            acc[0][0] += fa.x * gb.x; acc[0][1] += fa.x * gb.y;
            acc[0][2] += fa.x * gb.z; acc[0][3] += fa.x * gb.w;
            acc[1][0] += fa.y * gb.x; acc[1][1] += fa.y * gb.y;
            acc[1][2] += fa.y * gb.z; acc[1][3] += fa.y * gb.w;
            acc[2][0] += fa.z * gb.x; acc[2][1] += fa.z * gb.y;
            acc[2][2] += fa.z * gb.z; acc[2][3] += fa.z * gb.w;
            acc[3][0] += fa.w * gb.x; acc[3][1] += fa.w * gb.y;
            acc[3][2] += fa.w * gb.z; acc[3][3] += fa.w * gb.w;
        }
        #pragma unroll
        for (int i = 0; i < 4; i++) {
            float4 o;
            o.x = logit_of(acc[i][0]);
            o.y = logit_of(acc[i][1]);
            o.z = logit_of(acc[i][2]);
            o.w = logit_of(acc[i][3]);
            *reinterpret_cast<float4*>(&sI[(rowg * 4 + i) * 516 + jt + colg * 4]) = o;
        }
    }
    __syncthreads();

    // row softmax (unnormalized exp; 1/sum folded into GEMM2 epilogue)
    {
        int r = tid >> 3, sub = tid & 7;
        float m = -3.4e38f;
        for (int c = sub; c < TT; c += 8) m = fmaxf(m, sI[r * 516 + c]);
        #pragma unroll
        for (int o = 4; o > 0; o >>= 1) m = fmaxf(m, __shfl_xor_sync(0xffffffffu, m, o));
        float sum = 0.0f;
        for (int c = sub; c < TT; c += 8) {
            float e = __expf(sI[r * 516 + c] - m);
            sI[r * 516 + c] = e;
            sum += e;
        }
        #pragma unroll
        for (int o = 4; o > 0; o >>= 1) sum += __shfl_xor_sync(0xffffffffu, sum, o);
        if (sub == 0) sRow[r] = 1.0f / sum;
    }

    // GEMM2: out[16][64] = w(16x512) @ X(512x64), streaming X through smem
    float acc2[4][2];
    #pragma unroll
    for (int i = 0; i < 4; i++) { acc2[i][0] = 0.0f; acc2[i][1] = 0.0f; }
    float* sX = sG;          // [128][66]
    int colg2 = tid & 31;    // cols colg2*2, colg2*2+1

    for (int kt = 0; kt < TT; kt += 128) {
        __syncthreads();
        for (int i = tid; i < 128 * 64; i += 128) {
            int tl = i >> 6, dd = i & 63;
            sX[tl * 66 + dd] = xb[(kt + tl) * 64 + dd];
        }
        __syncthreads();
        #pragma unroll 2
        for (int k = 0; k < 128; k++) {
            float w0 = sI[(rowg * 4 + 0) * 516 + kt + k];
            float w1 = sI[(rowg * 4 + 1) * 516 + kt + k];
            float w2 = sI[(rowg * 4 + 2) * 516 + kt + k];
            float w3 = sI[(rowg * 4 + 3) * 516 + kt + k];
            float2 xv = *reinterpret_cast<const float2*>(&sX[k * 66 + colg2 * 2]);
            acc2[0][0] += w0 * xv.x; acc2[0][1] += w0 * xv.y;
            acc2[1][0] += w1 * xv.x; acc2[1][1] += w1 * xv.y;
            acc2[2][0] += w2 * xv.x; acc2[2][1] += w2 * xv.y;
            acc2[3][0] += w3 * xv.x; acc2[3][1] += w3 * xv.y;
        }
    }

    float a = 0.01f * rsp[0];
    #pragma unroll
    for (int i = 0; i < 4; i++) {
        int r = rowg * 4 + i;
        int trow = r0 + r;
        float invs = sRow[r];
        #pragma unroll
        for (int j = 0; j < 2; j++) {
            int c = colg2 * 2 + j;
            float xa = acc2[i][j] * invs;
            float xo = xb[trow * 64 + c];
            float x1 = 0.5f * xo + 0.5f * xa;
            float xn = x1 + a * (xa - x1);
            xout[b * TT * DD + trow * 64 + c] = xn;
        }
    }
}

// ---------------------------------------------------------------------------
// cov: per (batch, 16-row slab of D) covariance via sum(x_d x_e) - T*m_d*m_e
// grid (4 dg, 4 b), 256 threads. smem: x[512][65] + mean[64]
// ---------------------------------------------------------------------------
__global__ void cov_kernel(const float* __restrict__ x, float* __restrict__ cov) {
    extern __shared__ float sm[];
    float* sX = sm;                 // 512*65
    float* sM = sm + 512 * 65;      // 64
    int dg = blockIdx.x, b = blockIdx.y;
    const float* xb = x + b * TT * DD;
    int tid = threadIdx.x;
    for (int i = tid; i < TT * DD; i += 256) {
        int t = i >> 6, c = i & 63;
        sX[t * 65 + c] = xb[i];
    }
    __syncthreads();
    if (tid < 64) {
        float s = 0.0f;
        for (int t = 0; t < TT; t++) s += sX[t * 65 + tid];
        sM[tid] = s * (1.0f / 512.0f);
    }
    __syncthreads();
    int e = tid & 63;
    int dsub = tid >> 6;            // 0..3
    int d0 = dg * 16 + dsub * 4;
    float a0 = 0, a1 = 0, a2 = 0, a3 = 0;
    for (int t = 0; t < TT; t++) {
        float xe = sX[t * 65 + e];
        a0 += sX[t * 65 + d0 + 0] * xe;
        a1 += sX[t * 65 + d0 + 1] * xe;
        a2 += sX[t * 65 + d0 + 2] * xe;
        a3 += sX[t * 65 + d0 + 3] * xe;
    }
    float invT = (float)(1.0 / (512.0 + 1e-8));
    float me = sM[e];
    float* cb = cov + b * 4096;
    cb[(d0 + 0) * 64 + e] = (a0 - 512.0f * sM[d0 + 0] * me) * invT;
    cb[(d0 + 1) * 64 + e] = (a1 - 512.0f * sM[d0 + 1] * me) * invT;
    cb[(d0 + 2) * 64 + e] = (a2 - 512.0f * sM[d0 + 2] * me) * invT;
    cb[(d0 + 3) * 64 + e] = (a3 - 512.0f * sM[d0 + 3] * me) * invT;
}

// ---------------------------------------------------------------------------
// phi + kappa: one block per batch, 128 threads
// ---------------------------------------------------------------------------
__global__ void phik_kernel(const float* __restrict__ x, const float* __restrict__ cov,
                            float* __restrict__ out_phi, float* __restrict__ out_kappa) {
    int b = blockIdx.x;
    int tid = threadIdx.x;
    __shared__ float var[64];
    __shared__ float scr[4], scr2[4];
    const float* cb = cov + b * 4096;
    if (tid < 64) var[tid] = fmaxf(cb[tid * 64 + tid], 1e-8f);
    __syncthreads();

    float s = 0.0f;
    for (int i = tid; i < 4096; i += 128) {
        int d = i >> 6, e = i & 63;
        if (d != e) {
            float denom = fmaxf(sqrtf(var[d] * var[e]), 1e-8f);
            float c = cb[i] / denom;
            c = fminf(fmaxf(c, -1.0f), 1.0f);
            s += fabsf(c);
        }
    }
    #pragma unroll
    for (int o = 16; o > 0; o >>= 1) s += __shfl_xor_sync(0xffffffffu, s, o);
    if ((tid & 31) == 0) scr[tid >> 5] = s;

    float kn = 0.0f;
    const float* xb = x + b * TT * DD;
    for (int t = tid; t < TT; t += 128) {
        float ss = 0.0f;
        #pragma unroll 8
        for (int dd = 0; dd < 64; dd++) {
            float v = xb[t * 64 + dd];
            ss += v * v;
        }
        kn += sqrtf(ss);
    }
    #pragma unroll
    for (int o = 16; o > 0; o >>= 1) kn += __shfl_xor_sync(0xffffffffu, kn, o);
    if ((tid & 31) == 0) scr2[tid >> 5] = kn;
    __syncthreads();
    if (tid == 0) {
        out_phi[b]   = (scr[0] + scr[1] + scr[2] + scr[3]) * (1.0f / 4096.0f);
        out_kappa[b] = (scr2[0] + scr2[1] + scr2[2] + scr2[3]) * (1.0f / 512.0f);
    }
}

// ---------------------------------------------------------------------------
extern "C" void kernel_launch(void* const* d_in, const int* in_sizes, int n_in,
                              void* d_out, int out_size) {
    (void)in_sizes; (void)n_in; (void)out_size;
    const float* x0 = (const float*)d_in[0];
    const float* rs = (const float*)d_in[1];
    float* out = (float*)d_out;

    float *pF, *pX1, *pCov;
    cudaGetSymbolAddress((void**)&pF, g_F);
    cudaGetSymbolAddress((void**)&pX1, g_X1);
    cudaGetSymbolAddress((void**)&pCov, g_Cov);

    const size_t attnSmem = (size_t)(KK * 16 + KK * 128 + 16 * 516 + 16) * sizeof(float);  // 143,680 B
    const size_t covSmem  = (size_t)(512 * 65 + 64) * sizeof(float);                        // 133,376 B
    cudaFuncSetAttribute(attn_kernel, cudaFuncAttributeMaxDynamicSharedMemorySize, (int)attnSmem);
    cudaFuncSetAttribute(cov_kernel,  cudaFuncAttributeMaxDynamicSharedMemorySize, (int)covSmem);

    // iteration 1
    prep_kernel<<<BB * TT, 64>>>(x0, pF);
    attn_kernel<<<128, 128, attnSmem>>>(pF, x0, pX1, rs);
    // iteration 2 (final x written straight into d_out)
    prep_kernel<<<BB * TT, 64>>>(pX1, pF);
    attn_kernel<<<128, 128, attnSmem>>>(pF, pX1, out, rs);
    // statistics
    cov_kernel<<<dim3(4, 4), 256, covSmem>>>(out, pCov);
    phik_kernel<<<BB, 128>>>(out, pCov, out + X_ELEMS, out + X_ELEMS + BB);
}

// round 2
// speedup vs baseline: 1.2553x; 1.2553x over previous
#include <cuda_runtime.h>
#include <math.h>

// Problem constants
#define BB 4
#define TT 512
#define DD 64
#define KK 192          // 3 expansion terms x 64
#define X_ELEMS (BB*TT*DD)   // 131072

// Scratch (no allocations allowed)
__device__ float g_F[BB * KK * TT];     // k-major feature matrix per batch
__device__ float g_X1[BB * TT * DD];    // intermediate x after iteration 1
__device__ float g_Cov[BB * DD * DD];   // covariance per batch

// ---------------------------------------------------------------------------
// prep: per-row simplex projection + feature construction
//   F[b][k][t]: k in [0,64)  -> sqrt(p_d)
//               k in [64,128)-> c2 / sqrt(p_d)         (c2^2 = eps/2)
//               k in [128,192)-> c3 / sqrt(p_d)^3      (c3^2 = eps^2/8)
// ---------------------------------------------------------------------------
__global__ void prep_kernel(const float* __restrict__ x, float* __restrict__ Fm) {
    const float EPSf = 1e-8f;
    const float C2 = 7.0710678118654755e-05f;   // sqrt(5e-9)
    const float C3 = 3.5355339059327378e-09f;   // sqrt(1.25e-17)
    int row = blockIdx.x;          // b*512 + t
    int d = threadIdx.x;           // 0..63
    float v = x[(row << 6) + d];
    // jax.nn.softplus = max(x,0) + log1p(exp(-|x|))
    float sp = fmaxf(v, 0.0f) + log1pf(expf(-fabsf(v)));

    float s = sp;
    #pragma unroll
    for (int o = 16; o > 0; o >>= 1) s += __shfl_xor_sync(0xffffffffu, s, o);
    __shared__ float sh[2], sh2[2];
    if ((d & 31) == 0) sh[d >> 5] = s;
    __syncthreads();
    float S = sh[0] + sh[1];
    float p = sp / (S + EPSf);
    p = fmaxf(p, EPSf);
    float s2 = p;
    #pragma unroll
    for (int o = 16; o > 0; o >>= 1) s2 += __shfl_xor_sync(0xffffffffu, s2, o);
    if ((d & 31) == 0) sh2[d >> 5] = s2;
    __syncthreads();
    float S2 = sh2[0] + sh2[1];
    p = p / (S2 + EPSf);

    float sq  = sqrtf(p);
    float inv = 1.0f / sq;
    int b = row >> 9, t = row & 511;
    float* Fb = Fm + b * (KK * TT);
    Fb[d * TT + t]          = sq;
    Fb[(64 + d) * TT + t]   = C2 * inv;
    Fb[(128 + d) * TT + t]  = C3 * (inv * inv * inv);
}

__device__ __forceinline__ float logit_of(float inr) {
    inr = fminf(inr, 1.0f - 1e-6f);
    inr = fmaxf(inr, -1.0f + 1e-6f);
    return -2.0f * acosf(inr);   // TEMPERATURE = 1
}

// ---------------------------------------------------------------------------
// attn: fused (inner GEMM -> logits -> softmax -> w@X -> residual mix)
// grid = 4 batches * 32 row-blocks = 128 blocks, 256 threads (2 k-groups).
// smem: sF[192][16] | sG[192][128] (reused as sX[128][66]) | sI[16][516]
//       | sPb[16][132] partial-combine buffer | sRow[16]
// ---------------------------------------------------------------------------
__global__ void __launch_bounds__(256) attn_kernel(
    const float* __restrict__ Fm, const float* __restrict__ xin,
    float* __restrict__ xout, const float* __restrict__ rsp) {
    extern __shared__ float smem[];
    float* sF   = smem;                   // 192*16 = 3072 floats
    float* sG   = smem + KK * 16;         // 192*128 = 24576 floats
    float* sI   = sG + KK * 128;          // 16*516 = 8256 floats
    float* sPb  = sI + 16 * 516;          // 16*132 = 2112 floats
    float* sRow = sPb + 16 * 132;         // 16

    int b  = blockIdx.x >> 5;
    int rb = blockIdx.x & 31;
    int r0 = rb * 16;
    const float* Fb = Fm + b * KK * TT;
    const float* xb = xin + b * TT * DD;
    int tid  = threadIdx.x;
    int grp  = tid >> 7;       // 0 or 1 : k-split group
    int ltid = tid & 127;

    // load F rows for this strip; fold term-3 minus sign into the A operand
    for (int i = tid; i < KK * 16; i += 256) {
        int k = i >> 4, r = i & 15;
        float v = Fb[k * TT + r0 + r];
        sF[i] = (k >= 128) ? -v : v;
    }

    int rowg = ltid >> 5;   // 0..3  (uniform within each warp -> broadcast loads)
    int colg = ltid & 31;   // 0..31 -> cols colg*4 .. +3 (within col tile)
    const float4* sF4 = reinterpret_cast<const float4*>(sF);
    const float4* sG4 = reinterpret_cast<const float4*>(sG);
    const int k0 = grp * 96;    // this group's k range: [k0, k0+96)

    for (int jt = 0; jt < TT; jt += 128) {
        __syncthreads();
        // load G column tile (k-major global => coalesced), 192 x 32 float4
        float4* dst = reinterpret_cast<float4*>(sG);
        for (int i = tid; i < KK * 32; i += 256) {
            int k = i >> 5, c4 = i & 31;
            dst[i] = reinterpret_cast<const float4*>(Fb + k * TT + jt)[c4];
        }
        __syncthreads();

        float acc[4][4];
        #pragma unroll
        for (int i = 0; i < 4; i++)
            #pragma unroll
            for (int j = 0; j < 4; j++) acc[i][j] = 0.0f;

        #pragma unroll 4
        for (int kk = 0; kk < 96; kk++) {
            int k = k0 + kk;
            float4 fa = sF4[(k << 2) + rowg];
            float4 gb = sG4[(k << 5) + colg];
            acc[0][0] += fa.x * gb.x; acc[0][1] += fa.x * gb.y;
            acc[0][2] += fa.x * gb.z; acc[0][3] += fa.x * gb.w;
            acc[1][0] += fa.y * gb.x; acc[1][1] += fa.y * gb.y;
            acc[1][2] += fa.y * gb.z; acc[1][3] += fa.y * gb.w;
            acc[2][0] += fa.z * gb.x; acc[2][1] += fa.z * gb.y;
            acc[2][2] += fa.z * gb.z; acc[2][3] += fa.z * gb.w;
            acc[3][0] += fa.w * gb.x; acc[3][1] += fa.w * gb.y;
            acc[3][2] += fa.w * gb.z; acc[3][3] += fa.w * gb.w;
        }
        // group 1 publishes partials, group 0 combines + logit
        if (grp == 1) {
            #pragma unroll
            for (int i = 0; i < 4; i++) {
                float4 o = make_float4(acc[i][0], acc[i][1], acc[i][2], acc[i][3]);
                *reinterpret_cast<float4*>(&sPb[(rowg * 4 + i) * 132 + colg * 4]) = o;
            }
        }
        __syncthreads();
        if (grp == 0) {
            #pragma unroll
            for (int i = 0; i < 4; i++) {
                float4 pb = *reinterpret_cast<const float4*>(&sPb[(rowg * 4 + i) * 132 + colg * 4]);
                float4 o;
                o.x = logit_of(acc[i][0] + pb.x);
                o.y = logit_of(acc[i][1] + pb.y);
                o.z = logit_of(acc[i][2] + pb.z);
                o.w = logit_of(acc[i][3] + pb.w);
                *reinterpret_cast<float4*>(&sI[(rowg * 4 + i) * 516 + jt + colg * 4]) = o;
            }
        }
    }
    __syncthreads();

    // row softmax (unnormalized exp; 1/sum folded into GEMM2 epilogue)
    {
        int r = tid >> 4, sub = tid & 15;
        float m = -3.4e38f;
        for (int c = sub; c < TT; c += 16) m = fmaxf(m, sI[r * 516 + c]);
        #pragma unroll
        for (int o = 8; o > 0; o >>= 1) m = fmaxf(m, __shfl_xor_sync(0xffffffffu, m, o));
        float sum = 0.0f;
        for (int c = sub; c < TT; c += 16) {
            float e = __expf(sI[r * 516 + c] - m);
            sI[r * 516 + c] = e;
            sum += e;
        }
        #pragma unroll
        for (int o = 8; o > 0; o >>= 1) sum += __shfl_xor_sync(0xffffffffu, sum, o);
        if (sub == 0) sRow[r] = 1.0f / sum;
    }
    __syncthreads();

    // GEMM2: out[16][64] = w(16x512) @ X(512x64), streaming X through smem.
    // k-split inside each 128-wide tile: group g handles k in [g*64, g*64+64)
    float acc2[4][2];
    #pragma unroll
    for (int i = 0; i < 4; i++) { acc2[i][0] = 0.0f; acc2[i][1] = 0.0f; }
    float* sX = sG;          // [128][66]
    int colg2 = ltid & 31;   // cols colg2*2, colg2*2+1

    for (int kt = 0; kt < TT; kt += 128) {
        __syncthreads();
        for (int i = tid; i < 128 * 64; i += 256) {
            int tl = i >> 6, dd = i & 63;
            sX[tl * 66 + dd] = xb[(kt + tl) * 64 + dd];
        }
        __syncthreads();
        int kb = grp * 64;
        #pragma unroll 4
        for (int kk = 0; kk < 64; kk++) {
            int k = kb + kk;
            float w0 = sI[(rowg * 4 + 0) * 516 + kt + k];
            float w1 = sI[(rowg * 4 + 1) * 516 + kt + k];
            float w2 = sI[(rowg * 4 + 2) * 516 + kt + k];
            float w3 = sI[(rowg * 4 + 3) * 516 + kt + k];
            float2 xv = *reinterpret_cast<const float2*>(&sX[k * 66 + colg2 * 2]);
            acc2[0][0] += w0 * xv.x; acc2[0][1] += w0 * xv.y;
            acc2[1][0] += w1 * xv.x; acc2[1][1] += w1 * xv.y;
            acc2[2][0] += w2 * xv.x; acc2[2][1] += w2 * xv.y;
            acc2[3][0] += w3 * xv.x; acc2[3][1] += w3 * xv.y;
        }
    }

    // combine GEMM2 partials through sPb (reused as [16][66])
    if (grp == 1) {
        #pragma unroll
        for (int i = 0; i < 4; i++) {
            float2 o = make_float2(acc2[i][0], acc2[i][1]);
            *reinterpret_cast<float2*>(&sPb[(rowg * 4 + i) * 66 + colg2 * 2]) = o;
        }
    }
    __syncthreads();
    if (grp == 0) {
        float a = 0.01f * rsp[0];
        #pragma unroll
        for (int i = 0; i < 4; i++) {
            int r = rowg * 4 + i;
            int trow = r0 + r;
            float invs = sRow[r];
            float2 pb = *reinterpret_cast<const float2*>(&sPb[r * 66 + colg2 * 2]);
            float p0 = acc2[i][0] + pb.x;
            float p1 = acc2[i][1] + pb.y;
            #pragma unroll
            for (int j = 0; j < 2; j++) {
                int c = colg2 * 2 + j;
                float xa = (j ? p1 : p0) * invs;
                float xo = xb[trow * 64 + c];
                float x1 = 0.5f * xo + 0.5f * xa;
                float xn = x1 + a * (xa - x1);
                xout[b * TT * DD + trow * 64 + c] = xn;
            }
        }
    }
}

// ---------------------------------------------------------------------------
// cov: per (batch, 16-row slab of D) covariance via sum(x_d x_e) - T*m_d*m_e
// grid (4 dg, 4 b), 256 threads. smem: x[512][65] + mean[64]
// ---------------------------------------------------------------------------
__global__ void cov_kernel(const float* __restrict__ x, float* __restrict__ cov) {
    extern __shared__ float sm[];
    float* sX = sm;                 // 512*65
    float* sM = sm + 512 * 65;      // 64
    int dg = blockIdx.x, b = blockIdx.y;
    const float* xb = x + b * TT * DD;
    int tid = threadIdx.x;
    for (int i = tid; i < TT * DD; i += 256) {
        int t = i >> 6, c = i & 63;
        sX[t * 65 + c] = xb[i];
    }
    __syncthreads();
    if (tid < 64) {
        float s = 0.0f;
        for (int t = 0; t < TT; t++) s += sX[t * 65 + tid];
        sM[tid] = s * (1.0f / 512.0f);
    }
    __syncthreads();
    int e = tid & 63;
    int dsub = tid >> 6;            // 0..3
    int d0 = dg * 16 + dsub * 4;
    float a0 = 0, a1 = 0, a2 = 0, a3 = 0;
    for (int t = 0; t < TT; t++) {
        float xe = sX[t * 65 + e];
        a0 += sX[t * 65 + d0 + 0] * xe;
        a1 += sX[t * 65 + d0 + 1] * xe;
        a2 += sX[t * 65 + d0 + 2] * xe;
        a3 += sX[t * 65 + d0 + 3] * xe;
    }
    float invT = (float)(1.0 / (512.0 + 1e-8));
    float me = sM[e];
    float* cb = cov + b * 4096;
    cb[(d0 + 0) * 64 + e] = (a0 - 512.0f * sM[d0 + 0] * me) * invT;
    cb[(d0 + 1) * 64 + e] = (a1 - 512.0f * sM[d0 + 1] * me) * invT;
    cb[(d0 + 2) * 64 + e] = (a2 - 512.0f * sM[d0 + 2] * me) * invT;
    cb[(d0 + 3) * 64 + e] = (a3 - 512.0f * sM[d0 + 3] * me) * invT;
}

// ---------------------------------------------------------------------------
// phi + kappa: one block per batch, 128 threads
// ---------------------------------------------------------------------------
__global__ void phik_kernel(const float* __restrict__ x, const float* __restrict__ cov,
                            float* __restrict__ out_phi, float* __restrict__ out_kappa) {
    int b = blockIdx.x;
    int tid = threadIdx.x;
    __shared__ float var[64];
    __shared__ float scr[4], scr2[4];
    const float* cb = cov + b * 4096;
    if (tid < 64) var[tid] = fmaxf(cb[tid * 64 + tid], 1e-8f);
    __syncthreads();

    float s = 0.0f;
    for (int i = tid; i < 4096; i += 128) {
        int d = i >> 6, e = i & 63;
        if (d != e) {
            float denom = fmaxf(sqrtf(var[d] * var[e]), 1e-8f);
            float c = cb[i] / denom;
            c = fminf(fmaxf(c, -1.0f), 1.0f);
            s += fabsf(c);
        }
    }
    #pragma unroll
    for (int o = 16; o > 0; o >>= 1) s += __shfl_xor_sync(0xffffffffu, s, o);
    if ((tid & 31) == 0) scr[tid >> 5] = s;

    float kn = 0.0f;
    const float* xb = x + b * TT * DD;
    for (int t = tid; t < TT; t += 128) {
        float ss = 0.0f;
        #pragma unroll 8
        for (int dd = 0; dd < 64; dd++) {
            float v = xb[t * 64 + dd];
            ss += v * v;
        }
        kn += sqrtf(ss);
    }
    #pragma unroll
    for (int o = 16; o > 0; o >>= 1) kn += __shfl_xor_sync(0xffffffffu, kn, o);
    if ((tid & 31) == 0) scr2[tid >> 5] = kn;
    __syncthreads();
    if (tid == 0) {
        out_phi[b]   = (scr[0] + scr[1] + scr[2] + scr[3]) * (1.0f / 4096.0f);
        out_kappa[b] = (scr2[0] + scr2[1] + scr2[2] + scr2[3]) * (1.0f / 512.0f);
    }
}

// ---------------------------------------------------------------------------
extern "C" void kernel_launch(void* const* d_in, const int* in_sizes, int n_in,
                              void* d_out, int out_size) {
    (void)in_sizes; (void)n_in; (void)out_size;
    const float* x0 = (const float*)d_in[0];
    const float* rs = (const float*)d_in[1];
    float* out = (float*)d_out;

    float *pF, *pX1, *pCov;
    cudaGetSymbolAddress((void**)&pF, g_F);
    cudaGetSymbolAddress((void**)&pX1, g_X1);
    cudaGetSymbolAddress((void**)&pCov, g_Cov);

    const size_t attnSmem = (size_t)(KK * 16 + KK * 128 + 16 * 516 + 16 * 132 + 16) * sizeof(float);
    const size_t covSmem  = (size_t)(512 * 65 + 64) * sizeof(float);
    cudaFuncSetAttribute(attn_kernel, cudaFuncAttributeMaxDynamicSharedMemorySize, (int)attnSmem);
    cudaFuncSetAttribute(cov_kernel,  cudaFuncAttributeMaxDynamicSharedMemorySize, (int)covSmem);

    // iteration 1
    prep_kernel<<<BB * TT, 64>>>(x0, pF);
    attn_kernel<<<128, 256, attnSmem>>>(pF, x0, pX1, rs);
    // iteration 2 (final x written straight into d_out)
    prep_kernel<<<BB * TT, 64>>>(pX1, pF);
    attn_kernel<<<128, 256, attnSmem>>>(pF, pX1, out, rs);
    // statistics
    cov_kernel<<<dim3(4, 4), 256, covSmem>>>(out, pCov);
    phik_kernel<<<BB, 128>>>(out, pCov, out + X_ELEMS, out + X_ELEMS + BB);
}

// round 3
// speedup vs baseline: 1.9968x; 1.5907x over previous
#include <cuda_runtime.h>
#include <math.h>

#define BB 4
#define TT 512
#define DD 64
#define KK 192
#define X_ELEMS (BB*TT*DD)

__device__ float g_F[BB * KK * TT];        // k-major features
__device__ float g_X1[BB * TT * DD];       // x after iter 1
__device__ float g_CovP[BB * 8 * DD * DD]; // per-slice Gram partials
__device__ float g_MeanP[BB * 8 * DD];     // per-slice column-sum partials

// ---------------------------------------------------------------------------
// prep: softplus -> double normalize -> features (k-major)
// ---------------------------------------------------------------------------
__global__ void prep_kernel(const float* __restrict__ x, float* __restrict__ Fm) {
    const float EPSf = 1e-8f;
    const float C2 = 7.0710678118654755e-05f;   // sqrt(eps/2)
    const float C3 = 3.5355339059327378e-09f;   // sqrt(eps^2/8)
    int row = blockIdx.x;          // b*512 + t
    int d = threadIdx.x;           // 0..63
    float v = x[(row << 6) + d];
    float sp = fmaxf(v, 0.0f) + log1pf(expf(-fabsf(v)));

    float s = sp;
    #pragma unroll
    for (int o = 16; o > 0; o >>= 1) s += __shfl_xor_sync(0xffffffffu, s, o);
    __shared__ float sh[2], sh2[2];
    if ((d & 31) == 0) sh[d >> 5] = s;
    __syncthreads();
    float S = sh[0] + sh[1];
    float p = sp / (S + EPSf);
    p = fmaxf(p, EPSf);
    float s2 = p;
    #pragma unroll
    for (int o = 16; o > 0; o >>= 1) s2 += __shfl_xor_sync(0xffffffffu, s2, o);
    if ((d & 31) == 0) sh2[d >> 5] = s2;
    __syncthreads();
    float S2 = sh2[0] + sh2[1];
    p = p / (S2 + EPSf);

    float sq  = sqrtf(p);
    float inv = 1.0f / sq;
    int b = row >> 9, t = row & 511;
    float* Fb = Fm + b * (KK * TT);
    Fb[d * TT + t]          = sq;
    Fb[(64 + d) * TT + t]   = C2 * inv;
    Fb[(128 + d) * TT + t]  = C3 * (inv * inv * inv);
}

__device__ __forceinline__ float logit_of(float inr) {
    inr = fminf(inr, 1.0f - 1e-6f);
    inr = fmaxf(inr, -1.0f + 1e-6f);
    return -2.0f * acosf(inr);
}

// ---------------------------------------------------------------------------
// attn: grid 128 (4 b x 32 row-strips), 512 threads = 4 k-split groups of 128.
// smem: sF[192][16] | sG[192][128] (reused sX[128][66]) | sI[16][516]
//       | sPb[4][16][132] | sRow[16]
// ---------------------------------------------------------------------------
__global__ void __launch_bounds__(512) attn_kernel(
    const float* __restrict__ Fm, const float* __restrict__ xin,
    float* __restrict__ xout, const float* __restrict__ rsp) {
    extern __shared__ float smem[];
    float* sF   = smem;                   // 3072
    float* sG   = smem + KK * 16;         // 24576
    float* sI   = sG + KK * 128;          // 8256
    float* sPb  = sI + 16 * 516;          // 4*16*132 = 8448
    float* sRow = sPb + 4 * 16 * 132;     // 16

    int b  = blockIdx.x >> 5;
    int rb = blockIdx.x & 31;
    int r0 = rb * 16;
    const float* Fb = Fm + b * KK * TT;
    const float* xb = xin + b * TT * DD;
    int tid  = threadIdx.x;
    int grp  = tid >> 7;       // 0..3
    int ltid = tid & 127;
    int rowg = ltid >> 5;      // 0..3 (uniform per warp)
    int colg = ltid & 31;

    // A-strip load; fold term-3 minus sign
    for (int i = tid; i < KK * 16; i += 512) {
        int k = i >> 4, r = i & 15;
        float v = Fb[k * TT + r0 + r];
        sF[i] = (k >= 128) ? -v : v;
    }

    const float4* sF4 = reinterpret_cast<const float4*>(sF);
    const float4* sG4 = reinterpret_cast<const float4*>(sG);
    const int k0 = grp * 48;

    // ---------------- GEMM1 + logits ----------------
    for (int jt = 0; jt < TT; jt += 128) {
        __syncthreads();
        float4* dst = reinterpret_cast<float4*>(sG);
        for (int i = tid; i < KK * 32; i += 512) {
            int k = i >> 5, c4 = i & 31;
            dst[i] = reinterpret_cast<const float4*>(Fb + k * TT + jt)[c4];
        }
        __syncthreads();

        float acc[4][4];
        #pragma unroll
        for (int i = 0; i < 4; i++)
            #pragma unroll
            for (int j = 0; j < 4; j++) acc[i][j] = 0.0f;

        #pragma unroll 4
        for (int kk = 0; kk < 48; kk++) {
            int k = k0 + kk;
            float4 fa = sF4[(k << 2) + rowg];
            float4 gb = sG4[(k << 5) + colg];
            acc[0][0] += fa.x * gb.x; acc[0][1] += fa.x * gb.y;
            acc[0][2] += fa.x * gb.z; acc[0][3] += fa.x * gb.w;
            acc[1][0] += fa.y * gb.x; acc[1][1] += fa.y * gb.y;
            acc[1][2] += fa.y * gb.z; acc[1][3] += fa.y * gb.w;
            acc[2][0] += fa.z * gb.x; acc[2][1] += fa.z * gb.y;
            acc[2][2] += fa.z * gb.z; acc[2][3] += fa.z * gb.w;
            acc[3][0] += fa.w * gb.x; acc[3][1] += fa.w * gb.y;
            acc[3][2] += fa.w * gb.z; acc[3][3] += fa.w * gb.w;
        }
        // publish all groups' partials
        #pragma unroll
        for (int i = 0; i < 4; i++) {
            float4 o = make_float4(acc[i][0], acc[i][1], acc[i][2], acc[i][3]);
            *reinterpret_cast<float4*>(&sPb[grp * 2112 + (rowg * 4 + i) * 132 + colg * 4]) = o;
        }
        __syncthreads();
        // combine + acos spread over all 512 threads (1 float4 each)
        {
            int r = tid >> 5, c4 = tid & 31;
            float4 s0 = *reinterpret_cast<const float4*>(&sPb[0 * 2112 + r * 132 + c4 * 4]);
            float4 s1 = *reinterpret_cast<const float4*>(&sPb[1 * 2112 + r * 132 + c4 * 4]);
            float4 s2 = *reinterpret_cast<const float4*>(&sPb[2 * 2112 + r * 132 + c4 * 4]);
            float4 s3 = *reinterpret_cast<const float4*>(&sPb[3 * 2112 + r * 132 + c4 * 4]);
            float4 o;
            o.x = logit_of(s0.x + s1.x + s2.x + s3.x);
            o.y = logit_of(s0.y + s1.y + s2.y + s3.y);
            o.z = logit_of(s0.z + s1.z + s2.z + s3.z);
            o.w = logit_of(s0.w + s1.w + s2.w + s3.w);
            *reinterpret_cast<float4*>(&sI[r * 516 + jt + c4 * 4]) = o;
        }
    }
    __syncthreads();

    // ---------------- softmax (1 warp per row) ----------------
    {
        int r = tid >> 5, sub = tid & 31;
        float m = -3.4e38f;
        for (int c = sub; c < TT; c += 32) m = fmaxf(m, sI[r * 516 + c]);
        #pragma unroll
        for (int o = 16; o > 0; o >>= 1) m = fmaxf(m, __shfl_xor_sync(0xffffffffu, m, o));
        float sum = 0.0f;
        for (int c = sub; c < TT; c += 32) {
            float e = __expf(sI[r * 516 + c] - m);
            sI[r * 516 + c] = e;
            sum += e;
        }
        #pragma unroll
        for (int o = 16; o > 0; o >>= 1) sum += __shfl_xor_sync(0xffffffffu, sum, o);
        if (sub == 0) sRow[r] = 1.0f / sum;
    }

    // ---------------- GEMM2: w(16x512) @ X(512x64), 4-way k-split ----------
    float acc2[4][2];
    #pragma unroll
    for (int i = 0; i < 4; i++) { acc2[i][0] = 0.0f; acc2[i][1] = 0.0f; }
    float* sX = sG;          // [128][66]
    int colg2 = ltid & 31;
    int kb = grp * 32;

    for (int kt = 0; kt < TT; kt += 128) {
        __syncthreads();
        for (int i = tid; i < 128 * 64; i += 512) {
            int tl = i >> 6, dd = i & 63;
            sX[tl * 66 + dd] = xb[(kt + tl) * 64 + dd];
        }
        __syncthreads();
        #pragma unroll 4
        for (int kk = 0; kk < 32; kk++) {
            int k = kb + kk;
            float w0 = sI[(rowg * 4 + 0) * 516 + kt + k];
            float w1 = sI[(rowg * 4 + 1) * 516 + kt + k];
            float w2 = sI[(rowg * 4 + 2) * 516 + kt + k];
            float w3 = sI[(rowg * 4 + 3) * 516 + kt + k];
            float2 xv = *reinterpret_cast<const float2*>(&sX[k * 66 + colg2 * 2]);
            acc2[0][0] += w0 * xv.x; acc2[0][1] += w0 * xv.y;
            acc2[1][0] += w1 * xv.x; acc2[1][1] += w1 * xv.y;
            acc2[2][0] += w2 * xv.x; acc2[2][1] += w2 * xv.y;
            acc2[3][0] += w3 * xv.x; acc2[3][1] += w3 * xv.y;
        }
    }
    // publish + combine + epilogue (1 float2 per thread)
    #pragma unroll
    for (int i = 0; i < 4; i++) {
        float2 o = make_float2(acc2[i][0], acc2[i][1]);
        *reinterpret_cast<float2*>(&sPb[grp * 1056 + (rowg * 4 + i) * 66 + colg2 * 2]) = o;
    }
    __syncthreads();
    {
        int r = tid >> 5, c2 = tid & 31;
        float2 s0 = *reinterpret_cast<const float2*>(&sPb[0 * 1056 + r * 66 + c2 * 2]);
        float2 s1 = *reinterpret_cast<const float2*>(&sPb[1 * 1056 + r * 66 + c2 * 2]);
        float2 s2 = *reinterpret_cast<const float2*>(&sPb[2 * 1056 + r * 66 + c2 * 2]);
        float2 s3 = *reinterpret_cast<const float2*>(&sPb[3 * 1056 + r * 66 + c2 * 2]);
        float a = 0.01f * rsp[0];
        float invs = sRow[r];
        int trow = r0 + r;
        float2 xo = *reinterpret_cast<const float2*>(&xb[trow * 64 + c2 * 2]);
        float xa0 = (s0.x + s1.x + s2.x + s3.x) * invs;
        float xa1 = (s0.y + s1.y + s2.y + s3.y) * invs;
        float x10 = 0.5f * xo.x + 0.5f * xa0;
        float x11 = 0.5f * xo.y + 0.5f * xa1;
        float2 xn = make_float2(x10 + a * (xa0 - x10), x11 + a * (xa1 - x11));
        *reinterpret_cast<float2*>(&xout[b * TT * DD + trow * 64 + c2 * 2]) = xn;
    }
}

// ---------------------------------------------------------------------------
// cov partials: grid (8 t-slices, 4 b), 256 threads.
// Each block: raw Gram partial Sxx over 64 t's + column-sum partial.
// ---------------------------------------------------------------------------
__global__ void __launch_bounds__(256) cov_kernel(const float* __restrict__ x) {
    __shared__ float sXc[64 * 64];
    int slice = blockIdx.x, b = blockIdx.y;
    int t0 = slice * 64;
    const float* xb = x + b * TT * DD + t0 * DD;
    int tid = threadIdx.x;
    for (int i = tid; i < 64 * 64; i += 256) sXc[i] = xb[i];
    __syncthreads();

    if (tid < 64) {
        float s = 0.0f;
        #pragma unroll 8
        for (int t = 0; t < 64; t++) s += sXc[t * 64 + tid];
        g_MeanP[(b * 8 + slice) * 64 + tid] = s;
    }

    int td = tid >> 4, te = tid & 15;
    int d0 = td * 4, e0 = te * 4;
    float a00=0,a01=0,a02=0,a03=0, a10=0,a11=0,a12=0,a13=0;
    float a20=0,a21=0,a22=0,a23=0, a30=0,a31=0,a32=0,a33=0;
    #pragma unroll 4
    for (int t = 0; t < 64; t++) {
        float4 dv = *reinterpret_cast<const float4*>(&sXc[t * 64 + d0]);
        float4 ev = *reinterpret_cast<const float4*>(&sXc[t * 64 + e0]);
        a00 += dv.x*ev.x; a01 += dv.x*ev.y; a02 += dv.x*ev.z; a03 += dv.x*ev.w;
        a10 += dv.y*ev.x; a11 += dv.y*ev.y; a12 += dv.y*ev.z; a13 += dv.y*ev.w;
        a20 += dv.z*ev.x; a21 += dv.z*ev.y; a22 += dv.z*ev.z; a23 += dv.z*ev.w;
        a30 += dv.w*ev.x; a31 += dv.w*ev.y; a32 += dv.w*ev.z; a33 += dv.w*ev.w;
    }
    float* cp = g_CovP + (b * 8 + slice) * 4096;
    *reinterpret_cast<float4*>(&cp[(d0+0)*64 + e0]) = make_float4(a00,a01,a02,a03);
    *reinterpret_cast<float4*>(&cp[(d0+1)*64 + e0]) = make_float4(a10,a11,a12,a13);
    *reinterpret_cast<float4*>(&cp[(d0+2)*64 + e0]) = make_float4(a20,a21,a22,a23);
    *reinterpret_cast<float4*>(&cp[(d0+3)*64 + e0]) = make_float4(a30,a31,a32,a33);
}

// ---------------------------------------------------------------------------
// phik: combine partials -> corr -> phi, plus kappa. grid 4, 256 threads.
// ---------------------------------------------------------------------------
__global__ void __launch_bounds__(256) phik_kernel(
    const float* __restrict__ x,
    float* __restrict__ out_phi, float* __restrict__ out_kappa) {
    int b = blockIdx.x;
    int tid = threadIdx.x;
    __shared__ float m[64], var[64];
    __shared__ float red[8], red2[8];
    const float invT = 1.0f / 512.0f;   // fp32(512 + 1e-8) == 512

    if (tid < 64) {
        float s = 0.0f;
        #pragma unroll
        for (int sl = 0; sl < 8; sl++) s += g_MeanP[(b * 8 + sl) * 64 + tid];
        m[tid] = s * invT;
    }
    __syncthreads();
    if (tid < 64) {
        float sdd = 0.0f;
        #pragma unroll
        for (int sl = 0; sl < 8; sl++) sdd += g_CovP[(b * 8 + sl) * 4096 + tid * 65];
        float cv = (sdd - 512.0f * m[tid] * m[tid]) * invT;
        var[tid] = fmaxf(cv, 1e-8f);
    }
    __syncthreads();

    // phi: each thread owns 16 coalesced elements per slice pass
    float sxx[16];
    #pragma unroll
    for (int j = 0; j < 16; j++) sxx[j] = 0.0f;
    #pragma unroll
    for (int sl = 0; sl < 8; sl++) {
        const float* cp = g_CovP + (b * 8 + sl) * 4096;
        #pragma unroll
        for (int j = 0; j < 16; j++) sxx[j] += cp[tid + j * 256];
    }
    float acc = 0.0f;
    #pragma unroll
    for (int j = 0; j < 16; j++) {
        int i = tid + j * 256;
        int d = i >> 6, e = i & 63;
        if (d != e) {
            float cv = (sxx[j] - 512.0f * m[d] * m[e]) * invT;
            float denom = fmaxf(sqrtf(var[d] * var[e]), 1e-8f);
            float c = fminf(fmaxf(cv / denom, -1.0f), 1.0f);
            acc += fabsf(c);
        }
    }
    #pragma unroll
    for (int o = 16; o > 0; o >>= 1) acc += __shfl_xor_sync(0xffffffffu, acc, o);
    if ((tid & 31) == 0) red[tid >> 5] = acc;

    // kappa
    float kn = 0.0f;
    const float* xb = x + b * TT * DD;
    for (int t = tid; t < TT; t += 256) {
        const float4* xr = reinterpret_cast<const float4*>(xb + t * 64);
        float ss = 0.0f;
        #pragma unroll
        for (int q = 0; q < 16; q++) {
            float4 v = xr[q];
            ss += v.x*v.x + v.y*v.y + v.z*v.z + v.w*v.w;
        }
        kn += sqrtf(ss);
    }
    #pragma unroll
    for (int o = 16; o > 0; o >>= 1) kn += __shfl_xor_sync(0xffffffffu, kn, o);
    if ((tid & 31) == 0) red2[tid >> 5] = kn;
    __syncthreads();
    if (tid == 0) {
        float p = 0, k = 0;
        #pragma unroll
        for (int w = 0; w < 8; w++) { p += red[w]; k += red2[w]; }
        out_phi[b]   = p * (1.0f / 4096.0f);
        out_kappa[b] = k * (1.0f / 512.0f);
    }
}

// ---------------------------------------------------------------------------
extern "C" void kernel_launch(void* const* d_in, const int* in_sizes, int n_in,
                              void* d_out, int out_size) {
    (void)in_sizes; (void)n_in; (void)out_size;
    const float* x0 = (const float*)d_in[0];
    const float* rs = (const float*)d_in[1];
    float* out = (float*)d_out;

    float *pF, *pX1;
    cudaGetSymbolAddress((void**)&pF, g_F);
    cudaGetSymbolAddress((void**)&pX1, g_X1);

    const size_t attnSmem = (size_t)(KK * 16 + KK * 128 + 16 * 516 + 4 * 16 * 132 + 16) * sizeof(float);
    cudaFuncSetAttribute(attn_kernel, cudaFuncAttributeMaxDynamicSharedMemorySize, (int)attnSmem);

    prep_kernel<<<BB * TT, 64>>>(x0, pF);
    attn_kernel<<<128, 512, attnSmem>>>(pF, x0, pX1, rs);
    prep_kernel<<<BB * TT, 64>>>(pX1, pF);
    attn_kernel<<<128, 512, attnSmem>>>(pF, pX1, out, rs);
    cov_kernel<<<dim3(8, 4), 256>>>(out);
    phik_kernel<<<BB, 256>>>(out, out + X_ELEMS, out + X_ELEMS + BB);
}

// round 5
// speedup vs baseline: 2.0768x; 1.0400x over previous
#include <cuda_runtime.h>
#include <cstdint>
#include <math.h>

#define BB 4
#define TT 512
#define DD 64
#define KK 192
#define X_ELEMS (BB*TT*DD)

__device__ float g_F[BB * KK * TT];
__device__ float g_X1[BB * TT * DD];
__device__ float g_CovP[BB * 8 * DD * DD];
__device__ float g_MeanP[BB * 8 * DD];

// ---------------------------------------------------------------------------
__global__ void prep_kernel(const float* __restrict__ x, float* __restrict__ Fm) {
    const float EPSf = 1e-8f;
    const float C2 = 7.0710678118654755e-05f;
    const float C3 = 3.5355339059327378e-09f;
    int row = blockIdx.x;
    int d = threadIdx.x;
    float v = x[(row << 6) + d];
    float sp = fmaxf(v, 0.0f) + log1pf(expf(-fabsf(v)));

    float s = sp;
    #pragma unroll
    for (int o = 16; o > 0; o >>= 1) s += __shfl_xor_sync(0xffffffffu, s, o);
    __shared__ float sh[2], sh2[2];
    if ((d & 31) == 0) sh[d >> 5] = s;
    __syncthreads();
    float S = sh[0] + sh[1];
    float p = sp / (S + EPSf);
    p = fmaxf(p, EPSf);
    float s2 = p;
    #pragma unroll
    for (int o = 16; o > 0; o >>= 1) s2 += __shfl_xor_sync(0xffffffffu, s2, o);
    if ((d & 31) == 0) sh2[d >> 5] = s2;
    __syncthreads();
    float S2 = sh2[0] + sh2[1];
    p = p / (S2 + EPSf);

    float sq  = sqrtf(p);
    float inv = 1.0f / sq;
    int b = row >> 9, t = row & 511;
    float* Fb = Fm + b * (KK * TT);
    Fb[d * TT + t]          = sq;
    Fb[(64 + d) * TT + t]   = C2 * inv;
    Fb[(128 + d) * TT + t]  = C3 * (inv * inv * inv);
}

__device__ __forceinline__ float logit_of(float inr) {
    inr = fminf(inr, 1.0f - 1e-6f);
    inr = fmaxf(inr, -1.0f + 1e-6f);
    return -2.0f * acosf(inr);
}

__device__ __forceinline__ void cp_async16(unsigned int saddr, const void* gaddr) {
    asm volatile("cp.async.cg.shared.global [%0], [%1], 16;\n" :: "r"(saddr), "l"(gaddr));
}
__device__ __forceinline__ void cp_commit() {
    asm volatile("cp.async.commit_group;\n" ::: "memory");
}
template<int N>
__device__ __forceinline__ void cp_wait() {
    asm volatile("cp.async.wait_group %0;\n" :: "n"(N) : "memory");
}

// ---------------------------------------------------------------------------
// attn: 256 blocks (4 b x 64 row-strips of 8), 256 threads = 4 k-groups of 64.
// 2 blocks/SM. G streamed in 48-k chunks, cp.async double-buffered.
// smem (floats): sF[1536] | sG[2*6144] | sI[8*516] | sPb[4*8*132] | sRow[8]
// total 22184 floats = 88,736 B
// ---------------------------------------------------------------------------
#define SG_CHUNK (48*128)

__global__ void __launch_bounds__(256, 2) attn_kernel(
    const float* __restrict__ Fm, const float* __restrict__ xin,
    float* __restrict__ xout, const float* __restrict__ rsp) {
    extern __shared__ float smem[];
    float* sF   = smem;                       // 1536
    float* sG   = smem + 1536;                // 12288
    float* sI   = sG + 2 * SG_CHUNK;          // 4128
    float* sPb  = sI + 8 * 516;               // 4224
    float* sRow = sPb + 4 * 8 * 132;          // 8

    int b  = blockIdx.x >> 6;
    int rb = blockIdx.x & 63;
    int r0 = rb * 8;
    const float* Fb = Fm + b * KK * TT;
    const float* xb = xin + b * TT * DD;
    int tid  = threadIdx.x;
    int grp  = tid >> 6;        // 0..3
    int ltid = tid & 63;
    int rowg = ltid >> 5;       // 0..1 (uniform per warp)
    int colg = ltid & 31;

    // A-strip: 192 x 8, term-3 sign folded
    for (int i = tid; i < KK * 8; i += 256) {
        int k = i >> 3, r = i & 7;
        float v = Fb[k * TT + r0 + r];
        sF[i] = (k >= 128) ? -v : v;
    }

    const float4* sF4 = reinterpret_cast<const float4*>(sF);
    unsigned int sG_base = (unsigned int)__cvta_generic_to_shared(sG);

    // ---------------- GEMM1 + logits ----------------
    for (int jt = 0; jt < TT; jt += 128) {
        float acc[4][4];
        #pragma unroll
        for (int i = 0; i < 4; i++)
            #pragma unroll
            for (int j = 0; j < 4; j++) acc[i][j] = 0.0f;

        // prologue: chunk 0 -> buf 0
        {
            __syncthreads();   // previous-tile consumers done with both buffers
            #pragma unroll
            for (int j = 0; j < 6; j++) {
                int i = tid + j * 256;          // 0..1535
                int kl = i >> 5, c4 = i & 31;
                cp_async16(sG_base + (unsigned)((kl * 128 + c4 * 4) * 4),
                           Fb + kl * TT + jt + c4 * 4);
            }
            cp_commit();
        }

        #pragma unroll
        for (int c = 0; c < 4; c++) {
            if (c > 0) __syncthreads();   // everyone done with buffer being overwritten
            if (c < 3) {
                int nb = (c + 1) & 1;
                #pragma unroll
                for (int j = 0; j < 6; j++) {
                    int i = tid + j * 256;
                    int kl = i >> 5, c4 = i & 31;
                    cp_async16(sG_base + (unsigned)((nb * SG_CHUNK + kl * 128 + c4 * 4) * 4),
                               Fb + ((c + 1) * 48 + kl) * TT + jt + c4 * 4);
                }
                cp_commit();
                cp_wait<1>();
            } else {
                cp_wait<0>();
            }
            __syncthreads();  // chunk c visible to all

            const float4* bufG4 = reinterpret_cast<const float4*>(sG + (c & 1) * SG_CHUNK);
            int kg0 = c * 48 + grp * 12;
            #pragma unroll
            for (int kk = 0; kk < 12; kk++) {
                float4 fa = sF4[((kg0 + kk) << 1) + rowg];
                float4 gb = bufG4[((grp * 12 + kk) << 5) + colg];
                acc[0][0] += fa.x * gb.x; acc[0][1] += fa.x * gb.y;
                acc[0][2] += fa.x * gb.z; acc[0][3] += fa.x * gb.w;
                acc[1][0] += fa.y * gb.x; acc[1][1] += fa.y * gb.y;
                acc[1][2] += fa.y * gb.z; acc[1][3] += fa.y * gb.w;
                acc[2][0] += fa.z * gb.x; acc[2][1] += fa.z * gb.y;
                acc[2][2] += fa.z * gb.z; acc[2][3] += fa.z * gb.w;
                acc[3][0] += fa.w * gb.x; acc[3][1] += fa.w * gb.y;
                acc[3][2] += fa.w * gb.z; acc[3][3] += fa.w * gb.w;
            }
        }

        // publish partials
        #pragma unroll
        for (int i = 0; i < 4; i++) {
            float4 o = make_float4(acc[i][0], acc[i][1], acc[i][2], acc[i][3]);
            *reinterpret_cast<float4*>(&sPb[grp * 1056 + (rowg * 4 + i) * 132 + colg * 4]) = o;
        }
        __syncthreads();
        // combine + acos (1 float4 per thread: 8 rows x 32 col-quads)
        {
            int r = tid >> 5, c4 = tid & 31;
            float4 s0 = *reinterpret_cast<const float4*>(&sPb[0 * 1056 + r * 132 + c4 * 4]);
            float4 s1 = *reinterpret_cast<const float4*>(&sPb[1 * 1056 + r * 132 + c4 * 4]);
            float4 s2 = *reinterpret_cast<const float4*>(&sPb[2 * 1056 + r * 132 + c4 * 4]);
            float4 s3 = *reinterpret_cast<const float4*>(&sPb[3 * 1056 + r * 132 + c4 * 4]);
            float4 o;
            o.x = logit_of(s0.x + s1.x + s2.x + s3.x);
            o.y = logit_of(s0.y + s1.y + s2.y + s3.y);
            o.z = logit_of(s0.z + s1.z + s2.z + s3.z);
            o.w = logit_of(s0.w + s1.w + s2.w + s3.w);
            *reinterpret_cast<float4*>(&sI[r * 516 + jt + c4 * 4]) = o;
        }
    }
    __syncthreads();

    // ---------------- softmax: 1 warp per row ----------------
    {
        int r = tid >> 5, sub = tid & 31;
        float m = -3.4e38f;
        for (int c = sub; c < TT; c += 32) m = fmaxf(m, sI[r * 516 + c]);
        #pragma unroll
        for (int o = 16; o > 0; o >>= 1) m = fmaxf(m, __shfl_xor_sync(0xffffffffu, m, o));
        float sum = 0.0f;
        for (int c = sub; c < TT; c += 32) {
            float e = __expf(sI[r * 516 + c] - m);
            sI[r * 516 + c] = e;
            sum += e;
        }
        #pragma unroll
        for (int o = 16; o > 0; o >>= 1) sum += __shfl_xor_sync(0xffffffffu, sum, o);
        if (sub == 0) sRow[r] = 1.0f / sum;
    }

    // ---------------- GEMM2: w(8x512) @ X(512x64), 4-way k-split -----------
    float acc2[4][2];
    #pragma unroll
    for (int i = 0; i < 4; i++) { acc2[i][0] = 0.0f; acc2[i][1] = 0.0f; }
    float* sX = sG;            // [128][68] = 8704 floats
    unsigned int sX_base = sG_base;
    int colg2 = ltid & 31;
    int kb = grp * 32;

    for (int kt = 0; kt < TT; kt += 128) {
        __syncthreads();
        #pragma unroll
        for (int j = 0; j < 8; j++) {
            int i = tid + j * 256;       // 0..2047 float4s
            int t = i >> 4, d4 = i & 15;
            cp_async16(sX_base + (unsigned)((t * 68 + d4 * 4) * 4),
                       xb + (kt + t) * 64 + d4 * 4);
        }
        cp_commit();
        cp_wait<0>();
        __syncthreads();
        #pragma unroll 4
        for (int kk = 0; kk < 32; kk++) {
            int k = kb + kk;
            float w0 = sI[(rowg * 4 + 0) * 516 + kt + k];
            float w1 = sI[(rowg * 4 + 1) * 516 + kt + k];
            float w2 = sI[(rowg * 4 + 2) * 516 + kt + k];
            float w3 = sI[(rowg * 4 + 3) * 516 + kt + k];
            float2 xv = *reinterpret_cast<const float2*>(&sX[k * 68 + colg2 * 2]);
            acc2[0][0] += w0 * xv.x; acc2[0][1] += w0 * xv.y;
            acc2[1][0] += w1 * xv.x; acc2[1][1] += w1 * xv.y;
            acc2[2][0] += w2 * xv.x; acc2[2][1] += w2 * xv.y;
            acc2[3][0] += w3 * xv.x; acc2[3][1] += w3 * xv.y;
        }
    }
    // publish + combine + epilogue
    #pragma unroll
    for (int i = 0; i < 4; i++) {
        float2 o = make_float2(acc2[i][0], acc2[i][1]);
        *reinterpret_cast<float2*>(&sPb[grp * 528 + (rowg * 4 + i) * 66 + colg2 * 2]) = o;
    }
    __syncthreads();
    {
        int r = tid >> 5, c2 = tid & 31;
        float2 s0 = *reinterpret_cast<const float2*>(&sPb[0 * 528 + r * 66 + c2 * 2]);
        float2 s1 = *reinterpret_cast<const float2*>(&sPb[1 * 528 + r * 66 + c2 * 2]);
        float2 s2 = *reinterpret_cast<const float2*>(&sPb[2 * 528 + r * 66 + c2 * 2]);
        float2 s3 = *reinterpret_cast<const float2*>(&sPb[3 * 528 + r * 66 + c2 * 2]);
        float a = 0.01f * rsp[0];
        float invs = sRow[r];
        int trow = r0 + r;
        float2 xo = *reinterpret_cast<const float2*>(&xb[trow * 64 + c2 * 2]);
        float xa0 = (s0.x + s1.x + s2.x + s3.x) * invs;
        float xa1 = (s0.y + s1.y + s2.y + s3.y) * invs;
        float x10 = 0.5f * xo.x + 0.5f * xa0;
        float x11 = 0.5f * xo.y + 0.5f * xa1;
        float2 xn = make_float2(x10 + a * (xa0 - x10), x11 + a * (xa1 - x11));
        *reinterpret_cast<float2*>(&xout[b * TT * DD + trow * 64 + c2 * 2]) = xn;
    }
}

// ---------------------------------------------------------------------------
__global__ void __launch_bounds__(256) cov_kernel(const float* __restrict__ x) {
    __shared__ float sXc[64 * 64];
    int slice = blockIdx.x, b = blockIdx.y;
    const float* xb = x + b * TT * DD + slice * 64 * DD;
    int tid = threadIdx.x;
    for (int i = tid; i < 64 * 64; i += 256) sXc[i] = xb[i];
    __syncthreads();

    if (tid < 64) {
        float s = 0.0f;
        #pragma unroll 8
        for (int t = 0; t < 64; t++) s += sXc[t * 64 + tid];
        g_MeanP[(b * 8 + slice) * 64 + tid] = s;
    }

    int td = tid >> 4, te = tid & 15;
    int d0 = td * 4, e0 = te * 4;
    float a00=0,a01=0,a02=0,a03=0, a10=0,a11=0,a12=0,a13=0;
    float a20=0,a21=0,a22=0,a23=0, a30=0,a31=0,a32=0,a33=0;
    #pragma unroll 4
    for (int t = 0; t < 64; t++) {
        float4 dv = *reinterpret_cast<const float4*>(&sXc[t * 64 + d0]);
        float4 ev = *reinterpret_cast<const float4*>(&sXc[t * 64 + e0]);
        a00 += dv.x*ev.x; a01 += dv.x*ev.y; a02 += dv.x*ev.z; a03 += dv.x*ev.w;
        a10 += dv.y*ev.x; a11 += dv.y*ev.y; a12 += dv.y*ev.z; a13 += dv.y*ev.w;
        a20 += dv.z*ev.x; a21 += dv.z*ev.y; a22 += dv.z*ev.z; a23 += dv.z*ev.w;
        a30 += dv.w*ev.x; a31 += dv.w*ev.y; a32 += dv.w*ev.z; a33 += dv.w*ev.w;
    }
    float* cp = g_CovP + (b * 8 + slice) * 4096;
    *reinterpret_cast<float4*>(&cp[(d0+0)*64 + e0]) = make_float4(a00,a01,a02,a03);
    *reinterpret_cast<float4*>(&cp[(d0+1)*64 + e0]) = make_float4(a10,a11,a12,a13);
    *reinterpret_cast<float4*>(&cp[(d0+2)*64 + e0]) = make_float4(a20,a21,a22,a23);
    *reinterpret_cast<float4*>(&cp[(d0+3)*64 + e0]) = make_float4(a30,a31,a32,a33);
}

// ---------------------------------------------------------------------------
__global__ void __launch_bounds__(256) phik_kernel(
    const float* __restrict__ x,
    float* __restrict__ out_phi, float* __restrict__ out_kappa) {
    int b = blockIdx.x;
    int tid = threadIdx.x;
    __shared__ float m[64], var[64];
    __shared__ float red[8], red2[8];
    const float invT = 1.0f / 512.0f;

    if (tid < 64) {
        float s = 0.0f;
        #pragma unroll
        for (int sl = 0; sl < 8; sl++) s += g_MeanP[(b * 8 + sl) * 64 + tid];
        m[tid] = s * invT;
    }
    __syncthreads();
    if (tid < 64) {
        float sdd = 0.0f;
        #pragma unroll
        for (int sl = 0; sl < 8; sl++) sdd += g_CovP[(b * 8 + sl) * 4096 + tid * 65];
        float cv = (sdd - 512.0f * m[tid] * m[tid]) * invT;
        var[tid] = fmaxf(cv, 1e-8f);
    }
    __syncthreads();

    float sxx[16];
    #pragma unroll
    for (int j = 0; j < 16; j++) sxx[j] = 0.0f;
    #pragma unroll
    for (int sl = 0; sl < 8; sl++) {
        const float* cp = g_CovP + (b * 8 + sl) * 4096;
        #pragma unroll
        for (int j = 0; j < 16; j++) sxx[j] += cp[tid + j * 256];
    }
    float acc = 0.0f;
    #pragma unroll
    for (int j = 0; j < 16; j++) {
        int i = tid + j * 256;
        int d = i >> 6, e = i & 63;
        if (d != e) {
            float cv = (sxx[j] - 512.0f * m[d] * m[e]) * invT;
            float denom = fmaxf(sqrtf(var[d] * var[e]), 1e-8f);
            float c = fminf(fmaxf(cv / denom, -1.0f), 1.0f);
            acc += fabsf(c);
        }
    }
    #pragma unroll
    for (int o = 16; o > 0; o >>= 1) acc += __shfl_xor_sync(0xffffffffu, acc, o);
    if ((tid & 31) == 0) red[tid >> 5] = acc;

    float kn = 0.0f;
    const float* xb = x + b * TT * DD;
    for (int t = tid; t < TT; t += 256) {
        const float4* xr = reinterpret_cast<const float4*>(xb + t * 64);
        float ss = 0.0f;
        #pragma unroll
        for (int q = 0; q < 16; q++) {
            float4 v = xr[q];
            ss += v.x*v.x + v.y*v.y + v.z*v.z + v.w*v.w;
        }
        kn += sqrtf(ss);
    }
    #pragma unroll
    for (int o = 16; o > 0; o >>= 1) kn += __shfl_xor_sync(0xffffffffu, kn, o);
    if ((tid & 31) == 0) red2[tid >> 5] = kn;
    __syncthreads();
    if (tid == 0) {
        float p = 0, k = 0;
        #pragma unroll
        for (int w = 0; w < 8; w++) { p += red[w]; k += red2[w]; }
        out_phi[b]   = p * (1.0f / 4096.0f);
        out_kappa[b] = k * (1.0f / 512.0f);
    }
}

// ---------------------------------------------------------------------------
extern "C" void kernel_launch(void* const* d_in, const int* in_sizes, int n_in,
                              void* d_out, int out_size) {
    (void)in_sizes; (void)n_in; (void)out_size;
    const float* x0 = (const float*)d_in[0];
    const float* rs = (const float*)d_in[1];
    float* out = (float*)d_out;

    float *pF, *pX1;
    cudaGetSymbolAddress((void**)&pF, g_F);
    cudaGetSymbolAddress((void**)&pX1, g_X1);

    const size_t attnSmem = (size_t)(1536 + 2 * SG_CHUNK + 8 * 516 + 4 * 8 * 132 + 8) * sizeof(float); // 88,736 B
    cudaFuncSetAttribute(attn_kernel, cudaFuncAttributeMaxDynamicSharedMemorySize, (int)attnSmem);

    prep_kernel<<<BB * TT, 64>>>(x0, pF);
    attn_kernel<<<256, 256, attnSmem>>>(pF, x0, pX1, rs);
    prep_kernel<<<BB * TT, 64>>>(pX1, pF);
    attn_kernel<<<256, 256, attnSmem>>>(pF, pX1, out, rs);
    cov_kernel<<<dim3(8, 4), 256>>>(out);
    phik_kernel<<<BB, 256>>>(out, out + X_ELEMS, out + X_ELEMS + BB);
}

// round 6
// speedup vs baseline: 2.2638x; 1.0901x over previous
#include <cuda_runtime.h>
#include <cstdint>
#include <math.h>

#define BB 4
#define TT 512
#define DD 64
#define KK 192
#define X_ELEMS (BB*TT*DD)
#define GBUF 2048          // 16k x 128 cols floats per G buffer

__device__ float g_F[BB * KK * TT];
__device__ float g_F2[BB * KK * TT];
__device__ float g_X1[BB * TT * DD];
__device__ float g_CovP[BB * 8 * DD * DD];
__device__ float g_MeanP[BB * 8 * DD];

// ---------------------------------------------------------------------------
__global__ void prep_kernel(const float* __restrict__ x, float* __restrict__ Fm) {
    const float EPSf = 1e-8f;
    const float C2 = 7.0710678118654755e-05f;
    const float C3 = 3.5355339059327378e-09f;
    int row = blockIdx.x;
    int d = threadIdx.x;
    float v = x[(row << 6) + d];
    float sp = fmaxf(v, 0.0f) + log1pf(expf(-fabsf(v)));

    float s = sp;
    #pragma unroll
    for (int o = 16; o > 0; o >>= 1) s += __shfl_xor_sync(0xffffffffu, s, o);
    __shared__ float sh[2], sh2[2];
    if ((d & 31) == 0) sh[d >> 5] = s;
    __syncthreads();
    float S = sh[0] + sh[1];
    float p = sp / (S + EPSf);
    p = fmaxf(p, EPSf);
    float s2 = p;
    #pragma unroll
    for (int o = 16; o > 0; o >>= 1) s2 += __shfl_xor_sync(0xffffffffu, s2, o);
    if ((d & 31) == 0) sh2[d >> 5] = s2;
    __syncthreads();
    float S2 = sh2[0] + sh2[1];
    p = p / (S2 + EPSf);

    float sq  = sqrtf(p);
    float inv = 1.0f / sq;
    int b = row >> 9, t = row & 511;
    float* Fb = Fm + b * (KK * TT);
    Fb[d * TT + t]          = sq;
    Fb[(64 + d) * TT + t]   = C2 * inv;
    Fb[(128 + d) * TT + t]  = C3 * (inv * inv * inv);
}

__device__ __forceinline__ float logit_of(float inr) {
    inr = fminf(inr, 1.0f - 1e-6f);
    inr = fmaxf(inr, -1.0f + 1e-6f);
    return -2.0f * acosf(inr);
}

__device__ __forceinline__ void cp_async16(unsigned int saddr, const void* gaddr) {
    asm volatile("cp.async.cg.shared.global [%0], [%1], 16;\n" :: "r"(saddr), "l"(gaddr));
}
__device__ __forceinline__ void cp_commit() {
    asm volatile("cp.async.commit_group;\n" ::: "memory");
}
template<int N>
__device__ __forceinline__ void cp_wait() {
    asm volatile("cp.async.wait_group %0;\n" :: "n"(N) : "memory");
}
// 64-thread group barrier (named barrier ids 1..4)
__device__ __forceinline__ void barg(int grp) {
    asm volatile("bar.sync %0, 64;" :: "r"(grp + 1) : "memory");
}

__device__ __forceinline__ void load_g_chunk(unsigned int base, const float* __restrict__ Fb,
                                             int c, int buf, int jt0, int ltid) {
    // chunk c: k rows [c*16, c*16+16), cols [jt0, jt0+128) -> 512 float4s / 64 thr
    #pragma unroll
    for (int j = 0; j < 8; j++) {
        int i = ltid + j * 64;
        int kl = i >> 5, c4 = i & 31;
        cp_async16(base + (unsigned)((buf * GBUF + kl * 128 + c4 * 4) * 4),
                   Fb + (c * 16 + kl) * TT + jt0 + c4 * 4);
    }
    cp_commit();
}

// ---------------------------------------------------------------------------
// attn: 256 blocks (4 b x 64 strips of 8 rows), 256 threads = 4 groups of 64.
// Group g owns output columns [g*128,(g+1)*128) in GEMM1 (full K, no combine),
// and k-slab [g*32+kt, ...) in GEMM2. Groups sync only via named barriers,
// except 3 full-block syncs (sF ready, softmax in, softmax out).
// smem floats: sF[1536] | sG[4*2*2048=16384] | sI[8*516=4128] | sPb[2112] | sRow[8]
// total 24168 floats = 96,672 B; 2 blocks/SM.
// ---------------------------------------------------------------------------
__global__ void __launch_bounds__(256, 2) attn_kernel(
    const float* __restrict__ Fm, const float* __restrict__ xin,
    float* __restrict__ xout, const float* __restrict__ rsp,
    float* __restrict__ Fout) {
    extern __shared__ float smem[];
    float* sF   = smem;                 // 1536
    float* sG   = smem + 1536;          // 16384
    float* sI   = sG + 16384;           // 4128
    float* sPb  = sI + 8 * 516;         // 2112
    float* sRow = sPb + 2112;           // 8

    int b  = blockIdx.x >> 6;
    int rb = blockIdx.x & 63;
    int r0 = rb * 8;
    const float* Fb = Fm + b * KK * TT;
    const float* xb = xin + b * TT * DD;
    int tid  = threadIdx.x;
    int grp  = tid >> 6;
    int ltid = tid & 63;
    int rowg = ltid >> 5;     // 0..1
    int colg = ltid & 31;

    // A-strip: 192 k x 8 rows, term-3 sign folded
    for (int i = tid; i < KK * 8; i += 256) {
        int k = i >> 3, r = i & 7;
        float v = Fb[k * TT + r0 + r];
        sF[i] = (k >= 128) ? -v : v;
    }
    __syncthreads();

    float* myG = sG + grp * 2 * GBUF;
    unsigned int myG_base = (unsigned int)__cvta_generic_to_shared(myG);
    const int jt0 = grp * 128;
    const float4* sF4 = reinterpret_cast<const float4*>(sF);

    // ---------------- GEMM1: full-K inner products for own column quarter ---
    float acc[4][4];
    #pragma unroll
    for (int i = 0; i < 4; i++)
        #pragma unroll
        for (int j = 0; j < 4; j++) acc[i][j] = 0.0f;

    load_g_chunk(myG_base, Fb, 0, 0, jt0, ltid);
    #pragma unroll 1
    for (int c = 0; c < 12; c++) {
        if (c < 11) {
            load_g_chunk(myG_base, Fb, c + 1, (c + 1) & 1, jt0, ltid);
            cp_wait<1>();
        } else {
            cp_wait<0>();
        }
        barg(grp);   // chunk c visible group-wide
        const float4* buf4 = reinterpret_cast<const float4*>(myG + (c & 1) * GBUF);
        int kbase = c * 16;
        #pragma unroll
        for (int kk = 0; kk < 16; kk++) {
            float4 fa = sF4[((kbase + kk) << 1) + rowg];
            float4 gb = buf4[(kk << 5) + colg];
            acc[0][0] += fa.x * gb.x; acc[0][1] += fa.x * gb.y;
            acc[0][2] += fa.x * gb.z; acc[0][3] += fa.x * gb.w;
            acc[1][0] += fa.y * gb.x; acc[1][1] += fa.y * gb.y;
            acc[1][2] += fa.y * gb.z; acc[1][3] += fa.y * gb.w;
            acc[2][0] += fa.z * gb.x; acc[2][1] += fa.z * gb.y;
            acc[2][2] += fa.z * gb.z; acc[2][3] += fa.z * gb.w;
            acc[3][0] += fa.w * gb.x; acc[3][1] += fa.w * gb.y;
            acc[3][2] += fa.w * gb.z; acc[3][3] += fa.w * gb.w;
        }
        barg(grp);   // group done with this buffer before it's overwritten
    }

    // logits straight into sI (no combine needed)
    #pragma unroll
    for (int i = 0; i < 4; i++) {
        float4 o;
        o.x = logit_of(acc[i][0]);
        o.y = logit_of(acc[i][1]);
        o.z = logit_of(acc[i][2]);
        o.w = logit_of(acc[i][3]);
        *reinterpret_cast<float4*>(&sI[(rowg * 4 + i) * 516 + jt0 + colg * 4]) = o;
    }
    __syncthreads();

    // ---------------- softmax: 1 warp per row ----------------
    {
        int r = tid >> 5, sub = tid & 31;
        float m = -3.4e38f;
        for (int c = sub; c < TT; c += 32) m = fmaxf(m, sI[r * 516 + c]);
        #pragma unroll
        for (int o = 16; o > 0; o >>= 1) m = fmaxf(m, __shfl_xor_sync(0xffffffffu, m, o));
        float sum = 0.0f;
        for (int c = sub; c < TT; c += 32) {
            float e = __expf(sI[r * 516 + c] - m);
            sI[r * 516 + c] = e;
            sum += e;
        }
        #pragma unroll
        for (int o = 16; o > 0; o >>= 1) sum += __shfl_xor_sync(0xffffffffu, sum, o);
        if (sub == 0) sRow[r] = 1.0f / sum;
    }
    __syncthreads();

    // ---------------- GEMM2: w(8x512) @ X(512x64), per-group k-slabs --------
    float acc2[4][2];
    #pragma unroll
    for (int i = 0; i < 4; i++) { acc2[i][0] = 0.0f; acc2[i][1] = 0.0f; }
    float* sX = sG + grp * 2176;   // [32][68]
    unsigned int sX_base = (unsigned int)__cvta_generic_to_shared(sX);
    int kb = grp * 32;

    #pragma unroll 1
    for (int kt = 0; kt < TT; kt += 128) {
        barg(grp);   // protect sX from previous tile's consumers
        #pragma unroll
        for (int j = 0; j < 8; j++) {
            int i = ltid + j * 64;     // 0..511 float4
            int t = i >> 4, d4 = i & 15;
            cp_async16(sX_base + (unsigned)((t * 68 + d4 * 4) * 4),
                       xb + (kt + kb + t) * 64 + d4 * 4);
        }
        cp_commit();
        cp_wait<0>();
        barg(grp);
        #pragma unroll 4
        for (int kk = 0; kk < 32; kk++) {
            int kw = kt + kb + kk;
            float w0 = sI[(rowg * 4 + 0) * 516 + kw];
            float w1 = sI[(rowg * 4 + 1) * 516 + kw];
            float w2 = sI[(rowg * 4 + 2) * 516 + kw];
            float w3 = sI[(rowg * 4 + 3) * 516 + kw];
            float2 xv = *reinterpret_cast<const float2*>(&sX[kk * 68 + colg * 2]);
            acc2[0][0] += w0 * xv.x; acc2[0][1] += w0 * xv.y;
            acc2[1][0] += w1 * xv.x; acc2[1][1] += w1 * xv.y;
            acc2[2][0] += w2 * xv.x; acc2[2][1] += w2 * xv.y;
            acc2[3][0] += w3 * xv.x; acc2[3][1] += w3 * xv.y;
        }
    }
    // publish + combine + epilogue (+ fused feature prep for next iteration)
    #pragma unroll
    for (int i = 0; i < 4; i++) {
        float2 o = make_float2(acc2[i][0], acc2[i][1]);
        *reinterpret_cast<float2*>(&sPb[grp * 528 + (rowg * 4 + i) * 66 + colg * 2]) = o;
    }
    __syncthreads();
    {
        int r = tid >> 5, c2 = tid & 31;
        float2 s0 = *reinterpret_cast<const float2*>(&sPb[0 * 528 + r * 66 + c2 * 2]);
        float2 s1 = *reinterpret_cast<const float2*>(&sPb[1 * 528 + r * 66 + c2 * 2]);
        float2 s2 = *reinterpret_cast<const float2*>(&sPb[2 * 528 + r * 66 + c2 * 2]);
        float2 s3 = *reinterpret_cast<const float2*>(&sPb[3 * 528 + r * 66 + c2 * 2]);
        float a = 0.01f * rsp[0];
        float invs = sRow[r];
        int trow = r0 + r;
        float2 xo = *reinterpret_cast<const float2*>(&xb[trow * 64 + c2 * 2]);
        float xa0 = (s0.x + s1.x + s2.x + s3.x) * invs;
        float xa1 = (s0.y + s1.y + s2.y + s3.y) * invs;
        float x10 = 0.5f * xo.x + 0.5f * xa0;
        float x11 = 0.5f * xo.y + 0.5f * xa1;
        float xn0 = x10 + a * (xa0 - x10);
        float xn1 = x11 + a * (xa1 - x11);
        *reinterpret_cast<float2*>(&xout[b * TT * DD + trow * 64 + c2 * 2]) =
            make_float2(xn0, xn1);

        if (Fout != nullptr) {
            // fused simplex projection + feature build for the next iteration
            const float EPSf = 1e-8f;
            const float C2c = 7.0710678118654755e-05f;
            const float C3c = 3.5355339059327378e-09f;
            float sp0 = fmaxf(xn0, 0.0f) + log1pf(expf(-fabsf(xn0)));
            float sp1 = fmaxf(xn1, 0.0f) + log1pf(expf(-fabsf(xn1)));
            float s = sp0 + sp1;
            #pragma unroll
            for (int o = 16; o > 0; o >>= 1) s += __shfl_xor_sync(0xffffffffu, s, o);
            float p0 = fmaxf(sp0 / (s + EPSf), EPSf);
            float p1 = fmaxf(sp1 / (s + EPSf), EPSf);
            float s2n = p0 + p1;
            #pragma unroll
            for (int o = 16; o > 0; o >>= 1) s2n += __shfl_xor_sync(0xffffffffu, s2n, o);
            float rs2 = 1.0f / (s2n + EPSf);
            p0 *= rs2; p1 *= rs2;
            float sq0 = sqrtf(p0), iv0 = 1.0f / sq0;
            float sq1 = sqrtf(p1), iv1 = 1.0f / sq1;
            float* Fo = Fout + b * KK * TT;
            int d0 = c2 * 2;
            Fo[d0 * TT + trow]            = sq0;
            Fo[(64 + d0) * TT + trow]     = C2c * iv0;
            Fo[(128 + d0) * TT + trow]    = C3c * (iv0 * iv0 * iv0);
            Fo[(d0 + 1) * TT + trow]       = sq1;
            Fo[(64 + d0 + 1) * TT + trow]  = C2c * iv1;
            Fo[(128 + d0 + 1) * TT + trow] = C3c * (iv1 * iv1 * iv1);
        }
    }
}

// ---------------------------------------------------------------------------
__global__ void __launch_bounds__(256) cov_kernel(const float* __restrict__ x) {
    __shared__ float sXc[64 * 64];
    int slice = blockIdx.x, b = blockIdx.y;
    const float* xb = x + b * TT * DD + slice * 64 * DD;
    int tid = threadIdx.x;
    for (int i = tid; i < 64 * 64; i += 256) sXc[i] = xb[i];
    __syncthreads();

    if (tid < 64) {
        float s = 0.0f;
        #pragma unroll 8
        for (int t = 0; t < 64; t++) s += sXc[t * 64 + tid];
        g_MeanP[(b * 8 + slice) * 64 + tid] = s;
    }

    int td = tid >> 4, te = tid & 15;
    int d0 = td * 4, e0 = te * 4;
    float a00=0,a01=0,a02=0,a03=0, a10=0,a11=0,a12=0,a13=0;
    float a20=0,a21=0,a22=0,a23=0, a30=0,a31=0,a32=0,a33=0;
    #pragma unroll 4
    for (int t = 0; t < 64; t++) {
        float4 dv = *reinterpret_cast<const float4*>(&sXc[t * 64 + d0]);
        float4 ev = *reinterpret_cast<const float4*>(&sXc[t * 64 + e0]);
        a00 += dv.x*ev.x; a01 += dv.x*ev.y; a02 += dv.x*ev.z; a03 += dv.x*ev.w;
        a10 += dv.y*ev.x; a11 += dv.y*ev.y; a12 += dv.y*ev.z; a13 += dv.y*ev.w;
        a20 += dv.z*ev.x; a21 += dv.z*ev.y; a22 += dv.z*ev.z; a23 += dv.z*ev.w;
        a30 += dv.w*ev.x; a31 += dv.w*ev.y; a32 += dv.w*ev.z; a33 += dv.w*ev.w;
    }
    float* cp = g_CovP + (b * 8 + slice) * 4096;
    *reinterpret_cast<float4*>(&cp[(d0+0)*64 + e0]) = make_float4(a00,a01,a02,a03);
    *reinterpret_cast<float4*>(&cp[(d0+1)*64 + e0]) = make_float4(a10,a11,a12,a13);
    *reinterpret_cast<float4*>(&cp[(d0+2)*64 + e0]) = make_float4(a20,a21,a22,a23);
    *reinterpret_cast<float4*>(&cp[(d0+3)*64 + e0]) = make_float4(a30,a31,a32,a33);
}

// ---------------------------------------------------------------------------
__global__ void __launch_bounds__(256) phik_kernel(
    const float* __restrict__ x,
    float* __restrict__ out_phi, float* __restrict__ out_kappa) {
    int b = blockIdx.x;
    int tid = threadIdx.x;
    __shared__ float m[64], var[64];
    __shared__ float red[8], red2[8];
    const float invT = 1.0f / 512.0f;

    if (tid < 64) {
        float s = 0.0f;
        #pragma unroll
        for (int sl = 0; sl < 8; sl++) s += g_MeanP[(b * 8 + sl) * 64 + tid];
        m[tid] = s * invT;
    }
    __syncthreads();
    if (tid < 64) {
        float sdd = 0.0f;
        #pragma unroll
        for (int sl = 0; sl < 8; sl++) sdd += g_CovP[(b * 8 + sl) * 4096 + tid * 65];
        float cv = (sdd - 512.0f * m[tid] * m[tid]) * invT;
        var[tid] = fmaxf(cv, 1e-8f);
    }
    __syncthreads();

    float sxx[16];
    #pragma unroll
    for (int j = 0; j < 16; j++) sxx[j] = 0.0f;
    #pragma unroll
    for (int sl = 0; sl < 8; sl++) {
        const float* cp = g_CovP + (b * 8 + sl) * 4096;
        #pragma unroll
        for (int j = 0; j < 16; j++) sxx[j] += cp[tid + j * 256];
    }
    float acc = 0.0f;
    #pragma unroll
    for (int j = 0; j < 16; j++) {
        int i = tid + j * 256;
        int d = i >> 6, e = i & 63;
        if (d != e) {
            float cv = (sxx[j] - 512.0f * m[d] * m[e]) * invT;
            float denom = fmaxf(sqrtf(var[d] * var[e]), 1e-8f);
            float c = fminf(fmaxf(cv / denom, -1.0f), 1.0f);
            acc += fabsf(c);
        }
    }
    #pragma unroll
    for (int o = 16; o > 0; o >>= 1) acc += __shfl_xor_sync(0xffffffffu, acc, o);
    if ((tid & 31) == 0) red[tid >> 5] = acc;

    float kn = 0.0f;
    const float* xb = x + b * TT * DD;
    for (int t = tid; t < TT; t += 256) {
        const float4* xr = reinterpret_cast<const float4*>(xb + t * 64);
        float ss = 0.0f;
        #pragma unroll
        for (int q = 0; q < 16; q++) {
            float4 v = xr[q];
            ss += v.x*v.x + v.y*v.y + v.z*v.z + v.w*v.w;
        }
        kn += sqrtf(ss);
    }
    #pragma unroll
    for (int o = 16; o > 0; o >>= 1) kn += __shfl_xor_sync(0xffffffffu, kn, o);
    if ((tid & 31) == 0) red2[tid >> 5] = kn;
    __syncthreads();
    if (tid == 0) {
        float p = 0, k = 0;
        #pragma unroll
        for (int w = 0; w < 8; w++) { p += red[w]; k += red2[w]; }
        out_phi[b]   = p * (1.0f / 4096.0f);
        out_kappa[b] = k * (1.0f / 512.0f);
    }
}

// ---------------------------------------------------------------------------
extern "C" void kernel_launch(void* const* d_in, const int* in_sizes, int n_in,
                              void* d_out, int out_size) {
    (void)in_sizes; (void)n_in; (void)out_size;
    const float* x0 = (const float*)d_in[0];
    const float* rs = (const float*)d_in[1];
    float* out = (float*)d_out;

    float *pF, *pF2, *pX1;
    cudaGetSymbolAddress((void**)&pF, g_F);
    cudaGetSymbolAddress((void**)&pF2, g_F2);
    cudaGetSymbolAddress((void**)&pX1, g_X1);

    const size_t attnSmem = (size_t)(1536 + 16384 + 8 * 516 + 2112 + 8) * sizeof(float); // 96,672 B
    cudaFuncSetAttribute(attn_kernel, cudaFuncAttributeMaxDynamicSharedMemorySize, (int)attnSmem);

    prep_kernel<<<BB * TT, 64>>>(x0, pF);
    attn_kernel<<<256, 256, attnSmem>>>(pF, x0, pX1, rs, pF2);   // iter 1 (+ fused prep for iter 2)
    attn_kernel<<<256, 256, attnSmem>>>(pF2, pX1, out, rs, nullptr); // iter 2
    cov_kernel<<<dim3(8, 4), 256>>>(out);
    phik_kernel<<<BB, 256>>>(out, out + X_ELEMS, out + X_ELEMS + BB);
}